// round 13
// baseline (speedup 1.0000x reference)
#include <cuda_runtime.h>
#include <mma.h>
#include <math.h>

using namespace nvcuda;

#define HEADS 16
#define DIM 64
#define NTOK 2048
#define CHID 1024
#define BATCH 2
#define SCALE 0.125f

__device__ float g_qkv[3UL * BATCH * HEADS * NTOK * DIM];
__device__ float g_inv[(size_t)BATCH * HEADS * NTOK];

typedef wmma::fragment<wmma::matrix_a, 16, 16, 8, wmma::precision::tf32, wmma::row_major> AFrag;
typedef wmma::fragment<wmma::matrix_b, 16, 16, 8, wmma::precision::tf32, wmma::col_major> BFragCol;
typedef wmma::fragment<wmma::matrix_b, 16, 16, 8, wmma::precision::tf32, wmma::row_major> BFragRow;
typedef wmma::fragment<wmma::accumulator, 16, 16, 8, float> CFrag;

__device__ __forceinline__ float tf32r(float x) { return wmma::__float_to_tf32(x); }
__device__ __forceinline__ float4 tf4(float4 v) {
    v.x = tf32r(v.x); v.y = tf32r(v.y); v.z = tf32r(v.z); v.w = tf32r(v.w);
    return v;
}
__device__ __forceinline__ void cp16(void* s, const void* g) {
    unsigned sa = (unsigned)__cvta_generic_to_shared(s);
    asm volatile("cp.async.cg.shared.global [%0], [%1], 16;" :: "r"(sa), "l"(g));
}
#define CP_COMMIT() asm volatile("cp.async.commit_group;")
#define CP_WAIT(n) asm volatile("cp.async.wait_group %0;" :: "n"(n))

#define GLD 28
#define KLD 68   // attn staging stride: gcd(68,32)=4 -> 2-way (72 was 4-way)

// ---------------- QKV projection GEMM (R11, unchanged: 405us measured) ----------------
__global__ __launch_bounds__(256, 2) void qkv_gemm(const float* __restrict__ X,
                                                   const float* __restrict__ Wt) {
    extern __shared__ float sm1[];
    float* As = sm1;
    float* Bs = sm1 + 2 * 128 * GLD;
    float* Cs = sm1;

    int t = threadIdx.x;
    int bm = blockIdx.y, bn = blockIdx.x;
    int w = t >> 5;
    int wr = w >> 1, wc = w & 1;
    int lrow = t >> 1;
    int lq = (t & 1) * 8;

    const float* Ag = X + (size_t)(bm * 128 + lrow) * 1024 + lq;
    const float* Bg = Wt + (size_t)(bn * 128 + lrow) * 1024 + lq;

    CFrag acc[2][4];
#pragma unroll
    for (int i = 0; i < 2; i++)
#pragma unroll
        for (int j = 0; j < 4; j++) wmma::fill_fragment(acc[i][j], 0.f);

    {
        float* ad = &As[lrow * GLD + lq];
        float* bd = &Bs[lrow * GLD + lq];
        cp16(ad, Ag); cp16(ad + 4, Ag + 4);
        cp16(bd, Bg); cp16(bd + 4, Bg + 4);
        CP_COMMIT();
    }

    int buf = 0;
    for (int k0 = 0; k0 < 1024; k0 += 16, buf ^= 1) {
        if (k0 + 16 < 1024) {
            float* ad = &As[(buf ^ 1) * (128 * GLD) + lrow * GLD + lq];
            float* bd = &Bs[(buf ^ 1) * (128 * GLD) + lrow * GLD + lq];
            cp16(ad, Ag + k0 + 16); cp16(ad + 4, Ag + k0 + 20);
            cp16(bd, Bg + k0 + 16); cp16(bd + 4, Bg + k0 + 20);
            CP_COMMIT();
            CP_WAIT(1);
        } else {
            CP_WAIT(0);
        }
        __syncthreads();
        float* A = As + buf * (128 * GLD);
        float* B = Bs + buf * (128 * GLD);
#pragma unroll
        for (int ks = 0; ks < 2; ks++) {
            AFrag af[2];
            BFragCol bf[4];
#pragma unroll
            for (int i = 0; i < 2; i++) {
                wmma::load_matrix_sync(af[i], &A[(wr * 32 + i * 16) * GLD + ks * 8], GLD);
#pragma unroll
                for (int e = 0; e < af[i].num_elements; e++) af[i].x[e] = tf32r(af[i].x[e]);
            }
#pragma unroll
            for (int j = 0; j < 4; j++) {
                wmma::load_matrix_sync(bf[j], &B[(wc * 64 + j * 16) * GLD + ks * 8], GLD);
#pragma unroll
                for (int e = 0; e < bf[j].num_elements; e++) bf[j].x[e] = tf32r(bf[j].x[e]);
            }
#pragma unroll
            for (int i = 0; i < 2; i++)
#pragma unroll
                for (int j = 0; j < 4; j++)
                    wmma::mma_sync(acc[i][j], af[i], bf[j], acc[i][j]);
        }
        __syncthreads();
    }

#pragma unroll
    for (int hf = 0; hf < 2; hf++) {
        if (wc == hf) {
#pragma unroll
            for (int i = 0; i < 2; i++)
#pragma unroll
                for (int j = 0; j < 4; j++)
                    wmma::store_matrix_sync(&Cs[(wr * 32 + i * 16) * 72 + j * 16],
                                            acc[i][j], 72, wmma::mem_row_major);
        }
        __syncthreads();
        int colbase = bn * 128 + hf * 64;
        int qkv = colbase >> 10;
        int hh = (colbase >> 6) & 15;
#pragma unroll
        for (int i = 0; i < 8; i++) {
            int fi = t + (i << 8);
            int row = fi >> 4;
            int c4 = fi & 15;
            int m = bm * 128 + row;
            int b = m >> 11, n = m & 2047;
            float4 v = tf4(*(const float4*)&Cs[row * 72 + c4 * 4]);
            float* dst = g_qkv + ((((size_t)qkv * BATCH + b) * HEADS + hh) * NTOK + n) * DIM + c4 * 4;
            *(float4*)dst = v;
        }
        __syncthreads();
    }
}

// ---------------- fused attention: single pass, conflict-reduced ----------------
__global__ __launch_bounds__(256, 2) void attn_fused(const void* __restrict__ mask_raw,
                                                     float* __restrict__ att_out,
                                                     float* __restrict__ w_out) {
    extern __shared__ float sm[];
    float* qs = sm;                     // [64][KLD]
    float* kv = qs + 64 * KLD;          // 2 x [128][KLD]  (rows 0-63 K, 64-127 V)
    float* sc = kv + 2 * 128 * KLD;     // [64][68]
    float* rowsum = sc + 64 * 68;       // [64]
    float* mjf = rowsum + 64;           // [2048] col mask as float (0 = masked)
    unsigned char* mr = (unsigned char*)(mjf + 2048);  // [64]

    __shared__ int s_is32;

    int t = threadIdx.x;
    int w = t >> 5;
    int wr = w >> 1;      // 16-row group
    int wh = w & 1;       // 32-col half
    int b = blockIdx.z, h = blockIdx.y;
    int row0 = blockIdx.x << 6;

    const float* Qg = g_qkv + (((size_t)(0 * BATCH + b) * HEADS + h) * NTOK + row0) * DIM;
    const float* Kg = g_qkv + (((size_t)(1 * BATCH + b) * HEADS + h) * NTOK) * DIM;
    const float* Vg = g_qkv + (((size_t)(2 * BATCH + b) * HEADS + h) * NTOK) * DIM;
    float* Wt = w_out + ((size_t)(b * HEADS + h) * NTOK + row0) * NTOK;

    // stage Q + chunk 0 (K rows 0-63, V rows 64-127)
#pragma unroll
    for (int i = 0; i < 4; i++) {
        int fi = t + (i << 8);
        int r = fi >> 4;
        int d4 = (fi & 15) << 2;
        cp16(&qs[r * KLD + d4], Qg + (size_t)r * DIM + d4);
    }
#pragma unroll
    for (int i = 0; i < 8; i++) {
        int fi = t + (i << 8);
        int r = fi >> 4;
        int d4 = (fi & 15) << 2;
        const float* src = (r < 64) ? (Kg + (size_t)r * DIM + d4)
                                    : (Vg + (size_t)(r - 64) * DIM + d4);
        cp16(&kv[r * KLD + d4], src);
    }
    CP_COMMIT();

    if (t == 0) {
        const unsigned int* mw = (const unsigned int*)mask_raw;
        int is32 = 1;
        for (int i = 0; i < 64; i++)
            if (mw[i] > 1u) { is32 = 0; break; }
        s_is32 = is32;
    }
    __syncthreads();
    {
        const int is32 = s_is32;
        const int* m32 = (const int*)mask_raw;
        const unsigned char* m8 = (const unsigned char*)mask_raw;
#pragma unroll
        for (int i = 0; i < 8; i++) {
            int j = t + (i << 8);
            int masked = is32 ? (m32[(size_t)b * NTOK + j] != 0)
                              : (m8[(size_t)b * NTOK + j] != 0);
            mjf[j] = masked ? 0.f : 1.f;
        }
        if (t < 64) {
            int idx = b * NTOK + row0 + t;
            int mv = is32 ? (m32[idx] != 0) : (m8[idx] != 0);
            mr[t] = (unsigned char)mv;
            rowsum[t] = 0.f;
        }
    }
    __syncthreads();

    AFrag aq[8];
    CFrag av[2];
#pragma unroll
    for (int dt = 0; dt < 2; dt++) wmma::fill_fragment(av[dt], 0.f);

    for (int cb = 0; cb < 32; cb++) {
        if (cb + 1 < 32) {
            float* dst = kv + ((cb + 1) & 1) * (128 * KLD);
#pragma unroll
            for (int i = 0; i < 8; i++) {
                int fi = t + (i << 8);
                int r = fi >> 4;
                int d4 = (fi & 15) << 2;
                const float* src = (r < 64) ? (Kg + (size_t)((cb + 1) * 64 + r) * DIM + d4)
                                            : (Vg + (size_t)((cb + 1) * 64 + (r - 64)) * DIM + d4);
                cp16(&dst[r * KLD + d4], src);
            }
            CP_COMMIT();
            CP_WAIT(1);
        } else {
            CP_WAIT(0);
        }
        __syncthreads();
        float* buf = kv + (cb & 1) * (128 * KLD);

        if (cb == 0) {
#pragma unroll
            for (int k = 0; k < 8; k++)
                wmma::load_matrix_sync(aq[k], &qs[(wr * 16) * KLD + k * 8], KLD);
        }

        // S = Q K^T : warp does 16 rows x 32 cols
#pragma unroll
        for (int c = 0; c < 2; c++) {
            CFrag acc;
            wmma::fill_fragment(acc, 0.f);
#pragma unroll
            for (int k = 0; k < 8; k++) {
                BFragCol bf;
                wmma::load_matrix_sync(bf, &buf[(wh * 32 + c * 16) * KLD + k * 8], KLD);
                wmma::mma_sync(acc, aq[k], bf, acc);
            }
            wmma::store_matrix_sync(&sc[(wr * 16) * 68 + wh * 32 + c * 16], acc, 68,
                                    wmma::mem_row_major);
        }
        __syncthreads();

        // e = exp(s*SCALE)*colmask (or 1 if row masked); fused gmem store; rowsum
        {
            int r = t >> 2;
            int c0 = (t & 3) << 4;
            bool rm = mr[r] != 0;
            const float* cmp = mjf + cb * 64 + c0;
            float* p = &sc[r * 68 + c0];
            float* gp = Wt + (size_t)r * NTOK + cb * 64 + c0;
            float lsum = 0.f;
#pragma unroll
            for (int j4 = 0; j4 < 4; j4++) {
                float4 v = *(const float4*)(p + j4 * 4);
                float4 cm = *(const float4*)(cmp + j4 * 4);
                float4 e;
                e.x = rm ? 1.f : __expf(v.x * SCALE) * cm.x;
                e.y = rm ? 1.f : __expf(v.y * SCALE) * cm.y;
                e.z = rm ? 1.f : __expf(v.z * SCALE) * cm.z;
                e.w = rm ? 1.f : __expf(v.w * SCALE) * cm.w;
                *(float4*)(p + j4 * 4) = e;
                *(float4*)(gp + j4 * 4) = e;   // unnormalized weights out
                lsum += e.x + e.y + e.z + e.w;
            }
            lsum += __shfl_xor_sync(0xffffffffu, lsum, 1);
            lsum += __shfl_xor_sync(0xffffffffu, lsum, 2);
            if ((t & 3) == 0) rowsum[r] += lsum;
        }
        __syncthreads();

        // AV += e @ V
#pragma unroll
        for (int k = 0; k < 8; k++) {
            AFrag ae;
            wmma::load_matrix_sync(ae, &sc[(wr * 16) * 68 + k * 8], 68);
#pragma unroll
            for (int e = 0; e < ae.num_elements; e++) ae.x[e] = tf32r(ae.x[e]);
#pragma unroll
            for (int dt = 0; dt < 2; dt++) {
                BFragRow bv;
                wmma::load_matrix_sync(bv, &buf[(64 + k * 8) * KLD + wh * 32 + dt * 16], KLD);
                wmma::mma_sync(av[dt], ae, bv, av[dt]);
            }
        }
        // guard: next iter's cp.async overwrites the buffer just read
        __syncthreads();
    }

    if (t < 64) {
        float inv = 1.f / rowsum[t];
        rowsum[t] = inv;
        g_inv[((size_t)(b * HEADS + h) * NTOK) + row0 + t] = inv;
    }

#pragma unroll
    for (int dt = 0; dt < 2; dt++)
        wmma::store_matrix_sync(&sc[(wr * 16) * 68 + wh * 32 + dt * 16], av[dt], 68,
                                wmma::mem_row_major);
    __syncthreads();
    {
        int r = t >> 2;
        int d0 = (t & 3) << 4;
        float inv = rowsum[r];
        float* dst = att_out + ((size_t)b * NTOK + row0 + r) * CHID + h * DIM + d0;
#pragma unroll
        for (int j4 = 0; j4 < 4; j4++) {
            float4 v = *(const float4*)&sc[r * 68 + d0 + j4 * 4];
            v.x *= inv; v.y *= inv; v.z *= inv; v.w *= inv;
            *(float4*)(dst + j4 * 4) = v;
        }
    }
}

// ---------------- normalize weights (full-chip parallel, roofline-bound) ----------------
__global__ __launch_bounds__(256) void normalize_w(float* __restrict__ w_out) {
    size_t nf4 = (size_t)BATCH * HEADS * NTOK * NTOK / 4;
    size_t stride = (size_t)gridDim.x * blockDim.x;
    for (size_t i = (size_t)blockIdx.x * blockDim.x + threadIdx.x; i < nf4; i += stride) {
        size_t fidx = i << 2;
        float inv = __ldg(&g_inv[fidx >> 11]);
        float4 v = *(float4*)(w_out + fidx);
        v.x *= inv; v.y *= inv; v.z *= inv; v.w *= inv;
        *(float4*)(w_out + fidx) = v;
    }
}

#define GEMM_SMEM (2 * 2 * 128 * GLD * 4)
#define ATT_SMEM ((64 * KLD + 2 * 128 * KLD + 64 * 68 + 64 + 2048) * 4 + 64)

extern "C" void kernel_launch(void* const* d_in, const int* in_sizes, int n_in,
                              void* d_out, int out_size) {
    (void)in_sizes; (void)n_in; (void)out_size;
    const float* X = (const float*)d_in[0];
    const float* W = (const float*)d_in[1];
    const void* mask = d_in[2];
    float* att = (float*)d_out;
    float* wts = (float*)d_out + (size_t)BATCH * NTOK * CHID;

    cudaFuncSetAttribute(qkv_gemm, cudaFuncAttributeMaxDynamicSharedMemorySize, GEMM_SMEM);
    cudaFuncSetAttribute(attn_fused, cudaFuncAttributeMaxDynamicSharedMemorySize, ATT_SMEM);

    qkv_gemm<<<dim3(24, 32), 256, GEMM_SMEM>>>(X, W);
    attn_fused<<<dim3(32, HEADS, BATCH), 256, ATT_SMEM>>>(mask, att, wts);
    normalize_w<<<4096, 256>>>(wts);
}

// round 14
// speedup vs baseline: 1.0312x; 1.0312x over previous
#include <cuda_runtime.h>
#include <mma.h>
#include <math.h>

using namespace nvcuda;

#define HEADS 16
#define DIM 64
#define NTOK 2048
#define CHID 1024
#define BATCH 2
#define SCALE 0.125f

__device__ float g_qkv[3UL * BATCH * HEADS * NTOK * DIM];
__device__ float g_inv[(size_t)BATCH * HEADS * NTOK];

typedef wmma::fragment<wmma::matrix_a, 16, 16, 8, wmma::precision::tf32, wmma::row_major> AFrag;
typedef wmma::fragment<wmma::matrix_b, 16, 16, 8, wmma::precision::tf32, wmma::col_major> BFragCol;
typedef wmma::fragment<wmma::matrix_b, 16, 16, 8, wmma::precision::tf32, wmma::row_major> BFragRow;
typedef wmma::fragment<wmma::accumulator, 16, 16, 8, float> CFrag;

__device__ __forceinline__ float tf32r(float x) { return wmma::__float_to_tf32(x); }
__device__ __forceinline__ void cp16(void* s, const void* g) {
    unsigned sa = (unsigned)__cvta_generic_to_shared(s);
    asm volatile("cp.async.cg.shared.global [%0], [%1], 16;" :: "r"(sa), "l"(g));
}
#define CP_COMMIT() asm volatile("cp.async.commit_group;")
#define CP_WAIT(n) asm volatile("cp.async.wait_group %0;" :: "n"(n))

#define SLD 20   // gemm k-slab stride (16 floats padded to 20; gcd(20,32)=4)
#define KLD 68   // attn staging stride

// ---------------- QKV GEMM: 256x128 CTA, 8 warps x (64x64), direct-gmem epilogue ----------------
__global__ __launch_bounds__(256, 1) void qkv_gemm(const float* __restrict__ X,
                                                   const float* __restrict__ Wt) {
    extern __shared__ float sm1[];
    float* As = sm1;                    // [2][256*SLD]
    float* Bs = sm1 + 2 * 256 * SLD;    // [2][128*SLD]

    int t = threadIdx.x;
    int bm = blockIdx.y, bn = blockIdx.x;
    int w = t >> 5;
    int wr = w >> 1;     // 0..3 : 64-row group
    int wc = w & 1;      // 0..1 : 64-col group

    const float* Ag = X + (size_t)bm * 256 * 1024;
    const float* Bg = Wt + (size_t)bn * 128 * 1024;

    CFrag acc[4][4];
#pragma unroll
    for (int i = 0; i < 4; i++)
#pragma unroll
        for (int j = 0; j < 4; j++) wmma::fill_fragment(acc[i][j], 0.f);

    // staging maps: A 1024 cp16 units (4/thread), B 512 (2/thread)
    int ar[4], ak[4], br[2], bk[2];
#pragma unroll
    for (int i = 0; i < 4; i++) {
        int u = t + (i << 8);
        ar[i] = u >> 2;
        ak[i] = (u & 3) << 2;
    }
#pragma unroll
    for (int i = 0; i < 2; i++) {
        int u = t + (i << 8);
        br[i] = u >> 2;
        bk[i] = (u & 3) << 2;
    }

    // prefetch slab 0
    {
#pragma unroll
        for (int i = 0; i < 4; i++)
            cp16(&As[ar[i] * SLD + ak[i]], Ag + (size_t)ar[i] * 1024 + ak[i]);
#pragma unroll
        for (int i = 0; i < 2; i++)
            cp16(&Bs[br[i] * SLD + bk[i]], Bg + (size_t)br[i] * 1024 + bk[i]);
        CP_COMMIT();
    }

    int buf = 0;
    for (int k0 = 0; k0 < 1024; k0 += 16, buf ^= 1) {
        if (k0 + 16 < 1024) {
            float* ad = As + (buf ^ 1) * (256 * SLD);
            float* bd = Bs + (buf ^ 1) * (128 * SLD);
#pragma unroll
            for (int i = 0; i < 4; i++)
                cp16(&ad[ar[i] * SLD + ak[i]], Ag + (size_t)ar[i] * 1024 + k0 + 16 + ak[i]);
#pragma unroll
            for (int i = 0; i < 2; i++)
                cp16(&bd[br[i] * SLD + bk[i]], Bg + (size_t)br[i] * 1024 + k0 + 16 + bk[i]);
            CP_COMMIT();
            CP_WAIT(1);
        } else {
            CP_WAIT(0);
        }
        __syncthreads();
        float* A = As + buf * (256 * SLD);
        float* B = Bs + buf * (128 * SLD);
#pragma unroll
        for (int ks = 0; ks < 2; ks++) {
            AFrag af[4];
            BFragCol bf[4];
#pragma unroll
            for (int i = 0; i < 4; i++) {
                wmma::load_matrix_sync(af[i], &A[(wr * 64 + i * 16) * SLD + ks * 8], SLD);
#pragma unroll
                for (int e = 0; e < af[i].num_elements; e++) af[i].x[e] = tf32r(af[i].x[e]);
            }
#pragma unroll
            for (int j = 0; j < 4; j++) {
                wmma::load_matrix_sync(bf[j], &B[(wc * 64 + j * 16) * SLD + ks * 8], SLD);
#pragma unroll
                for (int e = 0; e < bf[j].num_elements; e++) bf[j].x[e] = tf32r(bf[j].x[e]);
            }
#pragma unroll
            for (int i = 0; i < 4; i++)
#pragma unroll
                for (int j = 0; j < 4; j++)
                    wmma::mma_sync(acc[i][j], af[i], bf[j], acc[i][j]);
        }
        __syncthreads();
    }

    // epilogue: tf32-round in fragment, store straight to g_qkv (each 16x16 frag
    // lies in one (qkv,b,h) block: 64-aligned col tiles, 16-row frags)
#pragma unroll
    for (int j = 0; j < 4; j++) {
        int c0 = bn * 128 + wc * 64 + j * 16;
        int qkv = c0 >> 10;
        int hh = (c0 >> 6) & 15;
        int d0 = c0 & 63;
#pragma unroll
        for (int i = 0; i < 4; i++) {
            int m0 = bm * 256 + wr * 64 + i * 16;
            int b = m0 >> 11;
            int n0 = m0 & 2047;
#pragma unroll
            for (int e = 0; e < acc[i][j].num_elements; e++)
                acc[i][j].x[e] = tf32r(acc[i][j].x[e]);
            float* dst = g_qkv + ((((size_t)qkv * BATCH + b) * HEADS + hh) * NTOK + n0) * DIM + d0;
            wmma::store_matrix_sync(dst, acc[i][j], DIM, wmma::mem_row_major);
        }
    }
}

// ---------------- fused attention (R13, unchanged) ----------------
__global__ __launch_bounds__(256, 2) void attn_fused(const void* __restrict__ mask_raw,
                                                     float* __restrict__ att_out,
                                                     float* __restrict__ w_out) {
    extern __shared__ float sm[];
    float* qs = sm;                     // [64][KLD]
    float* kv = qs + 64 * KLD;          // 2 x [128][KLD]
    float* sc = kv + 2 * 128 * KLD;     // [64][68]
    float* rowsum = sc + 64 * 68;       // [64]
    float* mjf = rowsum + 64;           // [2048]
    unsigned char* mr = (unsigned char*)(mjf + 2048);  // [64]

    __shared__ int s_is32;

    int t = threadIdx.x;
    int w = t >> 5;
    int wr = w >> 1;
    int wh = w & 1;
    int b = blockIdx.z, h = blockIdx.y;
    int row0 = blockIdx.x << 6;

    const float* Qg = g_qkv + (((size_t)(0 * BATCH + b) * HEADS + h) * NTOK + row0) * DIM;
    const float* Kg = g_qkv + (((size_t)(1 * BATCH + b) * HEADS + h) * NTOK) * DIM;
    const float* Vg = g_qkv + (((size_t)(2 * BATCH + b) * HEADS + h) * NTOK) * DIM;
    float* Wt = w_out + ((size_t)(b * HEADS + h) * NTOK + row0) * NTOK;

#pragma unroll
    for (int i = 0; i < 4; i++) {
        int fi = t + (i << 8);
        int r = fi >> 4;
        int d4 = (fi & 15) << 2;
        cp16(&qs[r * KLD + d4], Qg + (size_t)r * DIM + d4);
    }
#pragma unroll
    for (int i = 0; i < 8; i++) {
        int fi = t + (i << 8);
        int r = fi >> 4;
        int d4 = (fi & 15) << 2;
        const float* src = (r < 64) ? (Kg + (size_t)r * DIM + d4)
                                    : (Vg + (size_t)(r - 64) * DIM + d4);
        cp16(&kv[r * KLD + d4], src);
    }
    CP_COMMIT();

    if (t == 0) {
        const unsigned int* mw = (const unsigned int*)mask_raw;
        int is32 = 1;
        for (int i = 0; i < 64; i++)
            if (mw[i] > 1u) { is32 = 0; break; }
        s_is32 = is32;
    }
    __syncthreads();
    {
        const int is32 = s_is32;
        const int* m32 = (const int*)mask_raw;
        const unsigned char* m8 = (const unsigned char*)mask_raw;
#pragma unroll
        for (int i = 0; i < 8; i++) {
            int j = t + (i << 8);
            int masked = is32 ? (m32[(size_t)b * NTOK + j] != 0)
                              : (m8[(size_t)b * NTOK + j] != 0);
            mjf[j] = masked ? 0.f : 1.f;
        }
        if (t < 64) {
            int idx = b * NTOK + row0 + t;
            int mv = is32 ? (m32[idx] != 0) : (m8[idx] != 0);
            mr[t] = (unsigned char)mv;
            rowsum[t] = 0.f;
        }
    }
    __syncthreads();

    AFrag aq[8];
    CFrag av[2];
#pragma unroll
    for (int dt = 0; dt < 2; dt++) wmma::fill_fragment(av[dt], 0.f);

    for (int cb = 0; cb < 32; cb++) {
        if (cb + 1 < 32) {
            float* dst = kv + ((cb + 1) & 1) * (128 * KLD);
#pragma unroll
            for (int i = 0; i < 8; i++) {
                int fi = t + (i << 8);
                int r = fi >> 4;
                int d4 = (fi & 15) << 2;
                const float* src = (r < 64) ? (Kg + (size_t)((cb + 1) * 64 + r) * DIM + d4)
                                            : (Vg + (size_t)((cb + 1) * 64 + (r - 64)) * DIM + d4);
                cp16(&dst[r * KLD + d4], src);
            }
            CP_COMMIT();
            CP_WAIT(1);
        } else {
            CP_WAIT(0);
        }
        __syncthreads();
        float* buf = kv + (cb & 1) * (128 * KLD);

        if (cb == 0) {
#pragma unroll
            for (int k = 0; k < 8; k++)
                wmma::load_matrix_sync(aq[k], &qs[(wr * 16) * KLD + k * 8], KLD);
        }

#pragma unroll
        for (int c = 0; c < 2; c++) {
            CFrag acc;
            wmma::fill_fragment(acc, 0.f);
#pragma unroll
            for (int k = 0; k < 8; k++) {
                BFragCol bf;
                wmma::load_matrix_sync(bf, &buf[(wh * 32 + c * 16) * KLD + k * 8], KLD);
                wmma::mma_sync(acc, aq[k], bf, acc);
            }
            wmma::store_matrix_sync(&sc[(wr * 16) * 68 + wh * 32 + c * 16], acc, 68,
                                    wmma::mem_row_major);
        }
        __syncthreads();

        {
            int r = t >> 2;
            int c0 = (t & 3) << 4;
            bool rm = mr[r] != 0;
            const float* cmp = mjf + cb * 64 + c0;
            float* p = &sc[r * 68 + c0];
            float* gp = Wt + (size_t)r * NTOK + cb * 64 + c0;
            float lsum = 0.f;
#pragma unroll
            for (int j4 = 0; j4 < 4; j4++) {
                float4 v = *(const float4*)(p + j4 * 4);
                float4 cm = *(const float4*)(cmp + j4 * 4);
                float4 e;
                e.x = rm ? 1.f : __expf(v.x * SCALE) * cm.x;
                e.y = rm ? 1.f : __expf(v.y * SCALE) * cm.y;
                e.z = rm ? 1.f : __expf(v.z * SCALE) * cm.z;
                e.w = rm ? 1.f : __expf(v.w * SCALE) * cm.w;
                *(float4*)(p + j4 * 4) = e;
                *(float4*)(gp + j4 * 4) = e;
                lsum += e.x + e.y + e.z + e.w;
            }
            lsum += __shfl_xor_sync(0xffffffffu, lsum, 1);
            lsum += __shfl_xor_sync(0xffffffffu, lsum, 2);
            if ((t & 3) == 0) rowsum[r] += lsum;
        }
        __syncthreads();

#pragma unroll
        for (int k = 0; k < 8; k++) {
            AFrag ae;
            wmma::load_matrix_sync(ae, &sc[(wr * 16) * 68 + k * 8], 68);
#pragma unroll
            for (int e = 0; e < ae.num_elements; e++) ae.x[e] = tf32r(ae.x[e]);
#pragma unroll
            for (int dt = 0; dt < 2; dt++) {
                BFragRow bv;
                wmma::load_matrix_sync(bv, &buf[(64 + k * 8) * KLD + wh * 32 + dt * 16], KLD);
                wmma::mma_sync(av[dt], ae, bv, av[dt]);
            }
        }
        __syncthreads();
    }

    if (t < 64) {
        float inv = 1.f / rowsum[t];
        rowsum[t] = inv;
        g_inv[((size_t)(b * HEADS + h) * NTOK) + row0 + t] = inv;
    }

#pragma unroll
    for (int dt = 0; dt < 2; dt++)
        wmma::store_matrix_sync(&sc[(wr * 16) * 68 + wh * 32 + dt * 16], av[dt], 68,
                                wmma::mem_row_major);
    __syncthreads();
    {
        int r = t >> 2;
        int d0 = (t & 3) << 4;
        float inv = rowsum[r];
        float* dst = att_out + ((size_t)b * NTOK + row0 + r) * CHID + h * DIM + d0;
#pragma unroll
        for (int j4 = 0; j4 < 4; j4++) {
            float4 v = *(const float4*)&sc[r * 68 + d0 + j4 * 4];
            v.x *= inv; v.y *= inv; v.z *= inv; v.w *= inv;
            *(float4*)(dst + j4 * 4) = v;
        }
    }
}

// ---------------- normalize weights (roofline-bound) ----------------
__global__ __launch_bounds__(256) void normalize_w(float* __restrict__ w_out) {
    size_t nf4 = (size_t)BATCH * HEADS * NTOK * NTOK / 4;
    size_t stride = (size_t)gridDim.x * blockDim.x;
    for (size_t i = (size_t)blockIdx.x * blockDim.x + threadIdx.x; i < nf4; i += stride) {
        size_t fidx = i << 2;
        float inv = __ldg(&g_inv[fidx >> 11]);
        float4 v = *(float4*)(w_out + fidx);
        v.x *= inv; v.y *= inv; v.z *= inv; v.w *= inv;
        *(float4*)(w_out + fidx) = v;
    }
}

#define GEMM_SMEM (2 * (256 + 128) * SLD * 4)
#define ATT_SMEM ((64 * KLD + 2 * 128 * KLD + 64 * 68 + 64 + 2048) * 4 + 64)

extern "C" void kernel_launch(void* const* d_in, const int* in_sizes, int n_in,
                              void* d_out, int out_size) {
    (void)in_sizes; (void)n_in; (void)out_size;
    const float* X = (const float*)d_in[0];
    const float* W = (const float*)d_in[1];
    const void* mask = d_in[2];
    float* att = (float*)d_out;
    float* wts = (float*)d_out + (size_t)BATCH * NTOK * CHID;

    cudaFuncSetAttribute(qkv_gemm, cudaFuncAttributeMaxDynamicSharedMemorySize, GEMM_SMEM);
    cudaFuncSetAttribute(attn_fused, cudaFuncAttributeMaxDynamicSharedMemorySize, ATT_SMEM);

    qkv_gemm<<<dim3(24, 16), 256, GEMM_SMEM>>>(X, W);
    attn_fused<<<dim3(32, HEADS, BATCH), 256, ATT_SMEM>>>(mask, att, wts);
    normalize_w<<<4096, 256>>>(wts);
}

// round 15
// speedup vs baseline: 1.0570x; 1.0250x over previous
#include <cuda_runtime.h>
#include <mma.h>
#include <math.h>

using namespace nvcuda;

#define HEADS 16
#define DIM 64
#define NTOK 2048
#define CHID 1024
#define BATCH 2
#define SCALE 0.125f

__device__ float g_qkv[3UL * BATCH * HEADS * NTOK * DIM];
__device__ float g_inv[(size_t)BATCH * HEADS * NTOK];

typedef wmma::fragment<wmma::matrix_a, 16, 16, 8, wmma::precision::tf32, wmma::row_major> AFrag;
typedef wmma::fragment<wmma::matrix_b, 16, 16, 8, wmma::precision::tf32, wmma::col_major> BFragCol;
typedef wmma::fragment<wmma::matrix_b, 16, 16, 8, wmma::precision::tf32, wmma::row_major> BFragRow;
typedef wmma::fragment<wmma::accumulator, 16, 16, 8, float> CFrag;

__device__ __forceinline__ float tf32r(float x) { return wmma::__float_to_tf32(x); }
__device__ __forceinline__ void cp16(void* s, const void* g) {
    unsigned sa = (unsigned)__cvta_generic_to_shared(s);
    asm volatile("cp.async.cg.shared.global [%0], [%1], 16;" :: "r"(sa), "l"(g));
}
#define CP_COMMIT() asm volatile("cp.async.commit_group;")
#define CP_WAIT(n) asm volatile("cp.async.wait_group %0;" :: "n"(n))

#define SLD 20
#define KLD 68

// ---------------- QKV GEMM (R14, unchanged: 365us measured) ----------------
__global__ __launch_bounds__(256, 1) void qkv_gemm(const float* __restrict__ X,
                                                   const float* __restrict__ Wt) {
    extern __shared__ float sm1[];
    float* As = sm1;
    float* Bs = sm1 + 2 * 256 * SLD;

    int t = threadIdx.x;
    int bm = blockIdx.y, bn = blockIdx.x;
    int w = t >> 5;
    int wr = w >> 1;
    int wc = w & 1;

    const float* Ag = X + (size_t)bm * 256 * 1024;
    const float* Bg = Wt + (size_t)bn * 128 * 1024;

    CFrag acc[4][4];
#pragma unroll
    for (int i = 0; i < 4; i++)
#pragma unroll
        for (int j = 0; j < 4; j++) wmma::fill_fragment(acc[i][j], 0.f);

    int ar[4], ak[4], br[2], bk[2];
#pragma unroll
    for (int i = 0; i < 4; i++) {
        int u = t + (i << 8);
        ar[i] = u >> 2;
        ak[i] = (u & 3) << 2;
    }
#pragma unroll
    for (int i = 0; i < 2; i++) {
        int u = t + (i << 8);
        br[i] = u >> 2;
        bk[i] = (u & 3) << 2;
    }

    {
#pragma unroll
        for (int i = 0; i < 4; i++)
            cp16(&As[ar[i] * SLD + ak[i]], Ag + (size_t)ar[i] * 1024 + ak[i]);
#pragma unroll
        for (int i = 0; i < 2; i++)
            cp16(&Bs[br[i] * SLD + bk[i]], Bg + (size_t)br[i] * 1024 + bk[i]);
        CP_COMMIT();
    }

    int buf = 0;
    for (int k0 = 0; k0 < 1024; k0 += 16, buf ^= 1) {
        if (k0 + 16 < 1024) {
            float* ad = As + (buf ^ 1) * (256 * SLD);
            float* bd = Bs + (buf ^ 1) * (128 * SLD);
#pragma unroll
            for (int i = 0; i < 4; i++)
                cp16(&ad[ar[i] * SLD + ak[i]], Ag + (size_t)ar[i] * 1024 + k0 + 16 + ak[i]);
#pragma unroll
            for (int i = 0; i < 2; i++)
                cp16(&bd[br[i] * SLD + bk[i]], Bg + (size_t)br[i] * 1024 + k0 + 16 + bk[i]);
            CP_COMMIT();
            CP_WAIT(1);
        } else {
            CP_WAIT(0);
        }
        __syncthreads();
        float* A = As + buf * (256 * SLD);
        float* B = Bs + buf * (128 * SLD);
#pragma unroll
        for (int ks = 0; ks < 2; ks++) {
            AFrag af[4];
            BFragCol bf[4];
#pragma unroll
            for (int i = 0; i < 4; i++) {
                wmma::load_matrix_sync(af[i], &A[(wr * 64 + i * 16) * SLD + ks * 8], SLD);
#pragma unroll
                for (int e = 0; e < af[i].num_elements; e++) af[i].x[e] = tf32r(af[i].x[e]);
            }
#pragma unroll
            for (int j = 0; j < 4; j++) {
                wmma::load_matrix_sync(bf[j], &B[(wc * 64 + j * 16) * SLD + ks * 8], SLD);
#pragma unroll
                for (int e = 0; e < bf[j].num_elements; e++) bf[j].x[e] = tf32r(bf[j].x[e]);
            }
#pragma unroll
            for (int i = 0; i < 4; i++)
#pragma unroll
                for (int j = 0; j < 4; j++)
                    wmma::mma_sync(acc[i][j], af[i], bf[j], acc[i][j]);
        }
        __syncthreads();
    }

#pragma unroll
    for (int j = 0; j < 4; j++) {
        int c0 = bn * 128 + wc * 64 + j * 16;
        int qkv = c0 >> 10;
        int hh = (c0 >> 6) & 15;
        int d0 = c0 & 63;
#pragma unroll
        for (int i = 0; i < 4; i++) {
            int m0 = bm * 256 + wr * 64 + i * 16;
            int b = m0 >> 11;
            int n0 = m0 & 2047;
#pragma unroll
            for (int e = 0; e < acc[i][j].num_elements; e++)
                acc[i][j].x[e] = tf32r(acc[i][j].x[e]);
            float* dst = g_qkv + ((((size_t)qkv * BATCH + b) * HEADS + hh) * NTOK + n0) * DIM + d0;
            wmma::store_matrix_sync(dst, acc[i][j], DIM, wmma::mem_row_major);
        }
    }
}

// ---------------- fused attention: warp-local chunk body, 1 barrier/chunk ----------------
__global__ __launch_bounds__(256, 2) void attn_fused(const void* __restrict__ mask_raw,
                                                     float* __restrict__ att_out,
                                                     float* __restrict__ w_out) {
    extern __shared__ float sm[];
    float* qs = sm;                     // [64][KLD]; reused as wh=1 AV buffer at end
    float* kv = qs + 64 * KLD;          // 2 x [128][KLD]  (K rows 0-63, V rows 64-127)
    float* sc = kv + 2 * 128 * KLD;     // [64][68]
    float* rowsum = sc + 64 * 68;       // [64]
    float* mjf = rowsum + 64;           // [2048]
    unsigned char* mr = (unsigned char*)(mjf + 2048);  // [64]

    __shared__ int s_is32;

    int t = threadIdx.x;
    int w = t >> 5, lane = t & 31;
    int wr = w >> 1;      // 16-row group
    int wh = w & 1;       // 32-col half / k-half
    int b = blockIdx.z, h = blockIdx.y;
    int row0 = blockIdx.x << 6;

    const float* Qg = g_qkv + (((size_t)(0 * BATCH + b) * HEADS + h) * NTOK + row0) * DIM;
    const float* Kg = g_qkv + (((size_t)(1 * BATCH + b) * HEADS + h) * NTOK) * DIM;
    const float* Vg = g_qkv + (((size_t)(2 * BATCH + b) * HEADS + h) * NTOK) * DIM;
    float* Wt = w_out + ((size_t)(b * HEADS + h) * NTOK + row0) * NTOK;

    // prologue: stage Q + chunk 0 (single group)
#pragma unroll
    for (int i = 0; i < 4; i++) {
        int fi = t + (i << 8);
        int r = fi >> 4;
        int d4 = (fi & 15) << 2;
        cp16(&qs[r * KLD + d4], Qg + (size_t)r * DIM + d4);
    }
#pragma unroll
    for (int i = 0; i < 8; i++) {
        int fi = t + (i << 8);
        int r = fi >> 4;
        int d4 = (fi & 15) << 2;
        const float* src = (r < 64) ? (Kg + (size_t)r * DIM + d4)
                                    : (Vg + (size_t)(r - 64) * DIM + d4);
        cp16(&kv[r * KLD + d4], src);
    }
    CP_COMMIT();

    if (t == 0) {
        const unsigned int* mw = (const unsigned int*)mask_raw;
        int is32 = 1;
        for (int i = 0; i < 64; i++)
            if (mw[i] > 1u) { is32 = 0; break; }
        s_is32 = is32;
    }
    __syncthreads();
    {
        const int is32 = s_is32;
        const int* m32 = (const int*)mask_raw;
        const unsigned char* m8 = (const unsigned char*)mask_raw;
#pragma unroll
        for (int i = 0; i < 8; i++) {
            int j = t + (i << 8);
            int masked = is32 ? (m32[(size_t)b * NTOK + j] != 0)
                              : (m8[(size_t)b * NTOK + j] != 0);
            mjf[j] = masked ? 0.f : 1.f;
        }
        if (t < 64) {
            int idx = b * NTOK + row0 + t;
            int mv = is32 ? (m32[idx] != 0) : (m8[idx] != 0);
            mr[t] = (unsigned char)mv;
            rowsum[t] = 0.f;
        }
    }
    __syncthreads();

    AFrag aq[8];
    CFrag av[4];
#pragma unroll
    for (int dt = 0; dt < 4; dt++) wmma::fill_fragment(av[dt], 0.f);

    for (int cb = 0; cb < 32; cb++) {
        // wait for chunk cb's data (the only outstanding group), then the single
        // barrier: makes staged data visible AND guards the other buffer's reuse
        CP_WAIT(0);
        __syncthreads();

        // issue prefetch for cb+1 into the other buffer (safe: everyone is past
        // reading it), overlapping with this chunk's compute
        if (cb + 1 < 32) {
            float* dst = kv + ((cb + 1) & 1) * (128 * KLD);
#pragma unroll
            for (int i = 0; i < 8; i++) {
                int fi = t + (i << 8);
                int r = fi >> 4;
                int d4 = (fi & 15) << 2;
                const float* src = (r < 64) ? (Kg + (size_t)((cb + 1) * 64 + r) * DIM + d4)
                                            : (Vg + (size_t)((cb + 1) * 64 + (r - 64)) * DIM + d4);
                cp16(&dst[r * KLD + d4], src);
            }
            CP_COMMIT();
        }
        float* buf = kv + (cb & 1) * (128 * KLD);

        if (cb == 0) {
#pragma unroll
            for (int k = 0; k < 8; k++)
                wmma::load_matrix_sync(aq[k], &qs[(wr * 16) * KLD + k * 8], KLD);
        }

        // ---- S: warp-owned 16x32 tile ----
#pragma unroll
        for (int c = 0; c < 2; c++) {
            CFrag acc;
            wmma::fill_fragment(acc, 0.f);
#pragma unroll
            for (int k = 0; k < 8; k++) {
                BFragCol bf;
                wmma::load_matrix_sync(bf, &buf[(wh * 32 + c * 16) * KLD + k * 8], KLD);
                wmma::mma_sync(acc, aq[k], bf, acc);
            }
            wmma::store_matrix_sync(&sc[(wr * 16) * 68 + wh * 32 + c * 16], acc, 68,
                                    wmma::mem_row_major);
        }
        __syncwarp();

        // ---- exp warp-local on own tile; fused gmem store; atomic rowsum ----
        {
            int r = (wr << 4) + (lane >> 1);
            int c0 = (wh << 5) + ((lane & 1) << 4);
            bool rm = mr[r] != 0;
            const float* cmp = mjf + cb * 64 + c0;
            float* p = &sc[r * 68 + c0];
            float* gp = Wt + (size_t)r * NTOK + cb * 64 + c0;
            float lsum = 0.f;
#pragma unroll
            for (int j4 = 0; j4 < 4; j4++) {
                float4 v = *(const float4*)(p + j4 * 4);
                float4 cm = *(const float4*)(cmp + j4 * 4);
                float4 e;
                e.x = rm ? 1.f : __expf(v.x * SCALE) * cm.x;
                e.y = rm ? 1.f : __expf(v.y * SCALE) * cm.y;
                e.z = rm ? 1.f : __expf(v.z * SCALE) * cm.z;
                e.w = rm ? 1.f : __expf(v.w * SCALE) * cm.w;
                *(float4*)(p + j4 * 4) = e;
                *(float4*)(gp + j4 * 4) = e;
                lsum += e.x + e.y + e.z + e.w;
            }
            lsum += __shfl_xor_sync(0xffffffffu, lsum, 1);
            if ((lane & 1) == 0) atomicAdd(&rowsum[r], lsum);
        }
        __syncwarp();

        // ---- AV: warp-local k-half (k = wh*32..wh*32+31), all 64 d-cols ----
#pragma unroll
        for (int ks = 0; ks < 4; ks++) {
            AFrag ae;
            wmma::load_matrix_sync(ae, &sc[(wr * 16) * 68 + (wh << 5) + ks * 8], 68);
#pragma unroll
            for (int e = 0; e < ae.num_elements; e++) ae.x[e] = tf32r(ae.x[e]);
#pragma unroll
            for (int dt = 0; dt < 4; dt++) {
                BFragRow bv;
                wmma::load_matrix_sync(bv, &buf[(64 + (wh << 5) + ks * 8) * KLD + dt * 16], KLD);
                wmma::mma_sync(av[dt], ae, bv, av[dt]);
            }
        }
        // no trailing barrier: next iteration's top barrier is the guard
    }

    __syncthreads();   // all AV reads + rowsum atomics complete
    if (t < 64) {
        float inv = 1.f / rowsum[t];
        rowsum[t] = inv;
        g_inv[((size_t)(b * HEADS + h) * NTOK) + row0 + t] = inv;
    }

    // reduce the two k-halves: wh=0 -> sc, wh=1 -> qs (Q dead)
    {
        float* dstbuf = wh ? qs : sc;
#pragma unroll
        for (int dt = 0; dt < 4; dt++)
            wmma::store_matrix_sync(&dstbuf[(wr * 16) * 68 + dt * 16], av[dt], 68,
                                    wmma::mem_row_major);
    }
    __syncthreads();
    {
        int r = t >> 2;
        int d0 = (t & 3) << 4;
        float inv = rowsum[r];
        float* dst = att_out + ((size_t)b * NTOK + row0 + r) * CHID + h * DIM + d0;
#pragma unroll
        for (int j4 = 0; j4 < 4; j4++) {
            float4 a = *(const float4*)&sc[r * 68 + d0 + j4 * 4];
            float4 c = *(const float4*)&qs[r * KLD + d0 + j4 * 4];
            float4 o;
            o.x = (a.x + c.x) * inv;
            o.y = (a.y + c.y) * inv;
            o.z = (a.z + c.z) * inv;
            o.w = (a.w + c.w) * inv;
            *(float4*)(dst + j4 * 4) = o;
        }
    }
}

// ---------------- normalize weights (roofline-bound) ----------------
__global__ __launch_bounds__(256) void normalize_w(float* __restrict__ w_out) {
    size_t nf4 = (size_t)BATCH * HEADS * NTOK * NTOK / 4;
    size_t stride = (size_t)gridDim.x * blockDim.x;
    for (size_t i = (size_t)blockIdx.x * blockDim.x + threadIdx.x; i < nf4; i += stride) {
        size_t fidx = i << 2;
        float inv = __ldg(&g_inv[fidx >> 11]);
        float4 v = *(float4*)(w_out + fidx);
        v.x *= inv; v.y *= inv; v.z *= inv; v.w *= inv;
        *(float4*)(w_out + fidx) = v;
    }
}

#define GEMM_SMEM (2 * (256 + 128) * SLD * 4)
#define ATT_SMEM ((64 * KLD + 2 * 128 * KLD + 64 * 68 + 64 + 2048) * 4 + 64)

extern "C" void kernel_launch(void* const* d_in, const int* in_sizes, int n_in,
                              void* d_out, int out_size) {
    (void)in_sizes; (void)n_in; (void)out_size;
    const float* X = (const float*)d_in[0];
    const float* W = (const float*)d_in[1];
    const void* mask = d_in[2];
    float* att = (float*)d_out;
    float* wts = (float*)d_out + (size_t)BATCH * NTOK * CHID;

    cudaFuncSetAttribute(qkv_gemm, cudaFuncAttributeMaxDynamicSharedMemorySize, GEMM_SMEM);
    cudaFuncSetAttribute(attn_fused, cudaFuncAttributeMaxDynamicSharedMemorySize, ATT_SMEM);

    qkv_gemm<<<dim3(24, 16), 256, GEMM_SMEM>>>(X, W);
    attn_fused<<<dim3(32, HEADS, BATCH), 256, ATT_SMEM>>>(mask, att, wts);
    normalize_w<<<4096, 256>>>(wts);
}

// round 16
// speedup vs baseline: 1.0931x; 1.0342x over previous
#include <cuda_runtime.h>
#include <mma.h>
#include <math.h>

using namespace nvcuda;

#define HEADS 16
#define DIM 64
#define NTOK 2048
#define CHID 1024
#define BATCH 2
#define SCALE 0.125f

__device__ float g_qkv[3UL * BATCH * HEADS * NTOK * DIM];
__device__ float g_inv[(size_t)BATCH * HEADS * NTOK];

typedef wmma::fragment<wmma::matrix_a, 16, 16, 8, wmma::precision::tf32, wmma::row_major> AFrag;
typedef wmma::fragment<wmma::matrix_b, 16, 16, 8, wmma::precision::tf32, wmma::col_major> BFragCol;
typedef wmma::fragment<wmma::matrix_b, 16, 16, 8, wmma::precision::tf32, wmma::row_major> BFragRow;
typedef wmma::fragment<wmma::accumulator, 16, 16, 8, float> CFrag;

__device__ __forceinline__ float tf32r(float x) { return wmma::__float_to_tf32(x); }
__device__ __forceinline__ void cp16(void* s, const void* g) {
    unsigned sa = (unsigned)__cvta_generic_to_shared(s);
    asm volatile("cp.async.cg.shared.global [%0], [%1], 16;" :: "r"(sa), "l"(g));
}
#define CP_COMMIT() asm volatile("cp.async.commit_group;")
#define CP_WAIT(n) asm volatile("cp.async.wait_group %0;" :: "n"(n))

#define SLD 20
#define KLD 68

// ---------------- QKV GEMM (R14, unchanged: 365us measured) ----------------
__global__ __launch_bounds__(256, 1) void qkv_gemm(const float* __restrict__ X,
                                                   const float* __restrict__ Wt) {
    extern __shared__ float sm1[];
    float* As = sm1;
    float* Bs = sm1 + 2 * 256 * SLD;

    int t = threadIdx.x;
    int bm = blockIdx.y, bn = blockIdx.x;
    int w = t >> 5;
    int wr = w >> 1;
    int wc = w & 1;

    const float* Ag = X + (size_t)bm * 256 * 1024;
    const float* Bg = Wt + (size_t)bn * 128 * 1024;

    CFrag acc[4][4];
#pragma unroll
    for (int i = 0; i < 4; i++)
#pragma unroll
        for (int j = 0; j < 4; j++) wmma::fill_fragment(acc[i][j], 0.f);

    int ar[4], ak[4], br[2], bk[2];
#pragma unroll
    for (int i = 0; i < 4; i++) {
        int u = t + (i << 8);
        ar[i] = u >> 2;
        ak[i] = (u & 3) << 2;
    }
#pragma unroll
    for (int i = 0; i < 2; i++) {
        int u = t + (i << 8);
        br[i] = u >> 2;
        bk[i] = (u & 3) << 2;
    }

    {
#pragma unroll
        for (int i = 0; i < 4; i++)
            cp16(&As[ar[i] * SLD + ak[i]], Ag + (size_t)ar[i] * 1024 + ak[i]);
#pragma unroll
        for (int i = 0; i < 2; i++)
            cp16(&Bs[br[i] * SLD + bk[i]], Bg + (size_t)br[i] * 1024 + bk[i]);
        CP_COMMIT();
    }

    int buf = 0;
    for (int k0 = 0; k0 < 1024; k0 += 16, buf ^= 1) {
        if (k0 + 16 < 1024) {
            float* ad = As + (buf ^ 1) * (256 * SLD);
            float* bd = Bs + (buf ^ 1) * (128 * SLD);
#pragma unroll
            for (int i = 0; i < 4; i++)
                cp16(&ad[ar[i] * SLD + ak[i]], Ag + (size_t)ar[i] * 1024 + k0 + 16 + ak[i]);
#pragma unroll
            for (int i = 0; i < 2; i++)
                cp16(&bd[br[i] * SLD + bk[i]], Bg + (size_t)br[i] * 1024 + k0 + 16 + bk[i]);
            CP_COMMIT();
            CP_WAIT(1);
        } else {
            CP_WAIT(0);
        }
        __syncthreads();
        float* A = As + buf * (256 * SLD);
        float* B = Bs + buf * (128 * SLD);
#pragma unroll
        for (int ks = 0; ks < 2; ks++) {
            AFrag af[4];
            BFragCol bf[4];
#pragma unroll
            for (int i = 0; i < 4; i++) {
                wmma::load_matrix_sync(af[i], &A[(wr * 64 + i * 16) * SLD + ks * 8], SLD);
#pragma unroll
                for (int e = 0; e < af[i].num_elements; e++) af[i].x[e] = tf32r(af[i].x[e]);
            }
#pragma unroll
            for (int j = 0; j < 4; j++) {
                wmma::load_matrix_sync(bf[j], &B[(wc * 64 + j * 16) * SLD + ks * 8], SLD);
#pragma unroll
                for (int e = 0; e < bf[j].num_elements; e++) bf[j].x[e] = tf32r(bf[j].x[e]);
            }
#pragma unroll
            for (int i = 0; i < 4; i++)
#pragma unroll
                for (int j = 0; j < 4; j++)
                    wmma::mma_sync(acc[i][j], af[i], bf[j], acc[i][j]);
        }
        __syncthreads();
    }

#pragma unroll
    for (int j = 0; j < 4; j++) {
        int c0 = bn * 128 + wc * 64 + j * 16;
        int qkv = c0 >> 10;
        int hh = (c0 >> 6) & 15;
        int d0 = c0 & 63;
#pragma unroll
        for (int i = 0; i < 4; i++) {
            int m0 = bm * 256 + wr * 64 + i * 16;
            int b = m0 >> 11;
            int n0 = m0 & 2047;
#pragma unroll
            for (int e = 0; e < acc[i][j].num_elements; e++)
                acc[i][j].x[e] = tf32r(acc[i][j].x[e]);
            float* dst = g_qkv + ((((size_t)qkv * BATCH + b) * HEADS + hh) * NTOK + n0) * DIM + d0;
            wmma::store_matrix_sync(dst, acc[i][j], DIM, wmma::mem_row_major);
        }
    }
}

// ---------------- fused attention: 4 warps x (32x32) tiles, low LDS redundancy ----------------
__global__ __launch_bounds__(128, 2) void attn_fused(const void* __restrict__ mask_raw,
                                                     float* __restrict__ att_out,
                                                     float* __restrict__ w_out) {
    extern __shared__ float sm[];
    float* qs = sm;                     // [64][68]; reused as wh=1 AV buffer at end
    float* kv = qs + 64 * KLD;          // 2 x [128][68]  (K rows 0-63, V rows 64-127)
    float* sc = kv + 2 * 128 * KLD;     // [64][68]
    float* rowsum = sc + 64 * 68;       // [64]
    float* mjf = rowsum + 64;           // [2048]
    unsigned char* mr = (unsigned char*)(mjf + 2048);  // [64]

    __shared__ int s_is32;

    int t = threadIdx.x;
    int w = t >> 5, lane = t & 31;
    int wr = w >> 1;      // 32-row group (0..1)
    int wh = w & 1;       // 32-col / k half
    int b = blockIdx.z, h = blockIdx.y;
    int row0 = blockIdx.x << 6;

    const float* Qg = g_qkv + (((size_t)(0 * BATCH + b) * HEADS + h) * NTOK + row0) * DIM;
    const float* Kg = g_qkv + (((size_t)(1 * BATCH + b) * HEADS + h) * NTOK) * DIM;
    const float* Vg = g_qkv + (((size_t)(2 * BATCH + b) * HEADS + h) * NTOK) * DIM;
    float* Wt = w_out + ((size_t)(b * HEADS + h) * NTOK + row0) * NTOK;

    // prologue: stage Q (1024 f4, 8/thread) + chunk 0 K/V (2048 f4, 16/thread)
#pragma unroll
    for (int i = 0; i < 8; i++) {
        int fi = t + (i << 7);
        int r = fi >> 4;
        int d4 = (fi & 15) << 2;
        cp16(&qs[r * KLD + d4], Qg + (size_t)r * DIM + d4);
    }
#pragma unroll
    for (int i = 0; i < 16; i++) {
        int fi = t + (i << 7);
        int r = fi >> 4;
        int d4 = (fi & 15) << 2;
        const float* src = (r < 64) ? (Kg + (size_t)r * DIM + d4)
                                    : (Vg + (size_t)(r - 64) * DIM + d4);
        cp16(&kv[r * KLD + d4], src);
    }
    CP_COMMIT();

    if (t == 0) {
        const unsigned int* mw = (const unsigned int*)mask_raw;
        int is32 = 1;
        for (int i = 0; i < 64; i++)
            if (mw[i] > 1u) { is32 = 0; break; }
        s_is32 = is32;
    }
    __syncthreads();
    {
        const int is32 = s_is32;
        const int* m32 = (const int*)mask_raw;
        const unsigned char* m8 = (const unsigned char*)mask_raw;
#pragma unroll
        for (int i = 0; i < 16; i++) {
            int j = t + (i << 7);
            int masked = is32 ? (m32[(size_t)b * NTOK + j] != 0)
                              : (m8[(size_t)b * NTOK + j] != 0);
            mjf[j] = masked ? 0.f : 1.f;
        }
        if (t < 64) {
            int idx = b * NTOK + row0 + t;
            int mv = is32 ? (m32[idx] != 0) : (m8[idx] != 0);
            mr[t] = (unsigned char)mv;
            rowsum[t] = 0.f;
        }
    }
    __syncthreads();

    AFrag aq[16];       // Q rows wr*32..+32, all 64 k: [i2][k] = aq[i2*8+k]
    CFrag av[2][4];     // AV accum: 32 rows x 64 d
#pragma unroll
    for (int i2 = 0; i2 < 2; i2++)
#pragma unroll
        for (int dt = 0; dt < 4; dt++) wmma::fill_fragment(av[i2][dt], 0.f);

    for (int cb = 0; cb < 32; cb++) {
        CP_WAIT(0);
        __syncthreads();

        if (cb + 1 < 32) {
            float* dst = kv + ((cb + 1) & 1) * (128 * KLD);
#pragma unroll
            for (int i = 0; i < 16; i++) {
                int fi = t + (i << 7);
                int r = fi >> 4;
                int d4 = (fi & 15) << 2;
                const float* src = (r < 64) ? (Kg + (size_t)((cb + 1) * 64 + r) * DIM + d4)
                                            : (Vg + (size_t)((cb + 1) * 64 + (r - 64)) * DIM + d4);
                cp16(&dst[r * KLD + d4], src);
            }
            CP_COMMIT();
        }
        float* buf = kv + (cb & 1) * (128 * KLD);

        if (cb == 0) {
#pragma unroll
            for (int i2 = 0; i2 < 2; i2++)
#pragma unroll
                for (int k = 0; k < 8; k++)
                    wmma::load_matrix_sync(aq[i2 * 8 + k],
                                           &qs[(wr * 32 + i2 * 16) * KLD + k * 8], KLD);
        }

        // ---- S: warp-owned 32x32 tile (each bf reused for 2 row sub-tiles) ----
#pragma unroll
        for (int c = 0; c < 2; c++) {
            CFrag acc0, acc1;
            wmma::fill_fragment(acc0, 0.f);
            wmma::fill_fragment(acc1, 0.f);
#pragma unroll
            for (int k = 0; k < 8; k++) {
                BFragCol bf;
                wmma::load_matrix_sync(bf, &buf[(wh * 32 + c * 16) * KLD + k * 8], KLD);
                wmma::mma_sync(acc0, aq[k], bf, acc0);
                wmma::mma_sync(acc1, aq[8 + k], bf, acc1);
            }
            wmma::store_matrix_sync(&sc[(wr * 32) * 68 + wh * 32 + c * 16], acc0, 68,
                                    wmma::mem_row_major);
            wmma::store_matrix_sync(&sc[(wr * 32 + 16) * 68 + wh * 32 + c * 16], acc1, 68,
                                    wmma::mem_row_major);
        }
        __syncwarp();

        // ---- exp on own 32x32 tile; fused gmem store; atomic rowsum ----
#pragma unroll
        for (int rr = 0; rr < 2; rr++) {
            int r = wr * 32 + rr * 16 + (lane >> 1);
            int c0 = wh * 32 + ((lane & 1) << 4);
            bool rm = mr[r] != 0;
            const float* cmp = mjf + cb * 64 + c0;
            float* p = &sc[r * 68 + c0];
            float* gp = Wt + (size_t)r * NTOK + cb * 64 + c0;
            float lsum = 0.f;
#pragma unroll
            for (int j4 = 0; j4 < 4; j4++) {
                float4 v = *(const float4*)(p + j4 * 4);
                float4 cm = *(const float4*)(cmp + j4 * 4);
                float4 e;
                e.x = rm ? 1.f : __expf(v.x * SCALE) * cm.x;
                e.y = rm ? 1.f : __expf(v.y * SCALE) * cm.y;
                e.z = rm ? 1.f : __expf(v.z * SCALE) * cm.z;
                e.w = rm ? 1.f : __expf(v.w * SCALE) * cm.w;
                *(float4*)(p + j4 * 4) = e;
                *(float4*)(gp + j4 * 4) = e;
                lsum += e.x + e.y + e.z + e.w;
            }
            lsum += __shfl_xor_sync(0xffffffffu, lsum, 1);
            if ((lane & 1) == 0) atomicAdd(&rowsum[r], lsum);
        }
        __syncwarp();

        // ---- AV: rows wr*32..+32, k-half wh, all 64 d (bv reused for 2 row tiles) ----
#pragma unroll
        for (int ks = 0; ks < 4; ks++) {
            AFrag ae0, ae1;
            wmma::load_matrix_sync(ae0, &sc[(wr * 32) * 68 + (wh << 5) + ks * 8], 68);
            wmma::load_matrix_sync(ae1, &sc[(wr * 32 + 16) * 68 + (wh << 5) + ks * 8], 68);
#pragma unroll
            for (int e = 0; e < ae0.num_elements; e++) {
                ae0.x[e] = tf32r(ae0.x[e]);
                ae1.x[e] = tf32r(ae1.x[e]);
            }
#pragma unroll
            for (int dt = 0; dt < 4; dt++) {
                BFragRow bv;
                wmma::load_matrix_sync(bv, &buf[(64 + (wh << 5) + ks * 8) * KLD + dt * 16], KLD);
                wmma::mma_sync(av[0][dt], ae0, bv, av[0][dt]);
                wmma::mma_sync(av[1][dt], ae1, bv, av[1][dt]);
            }
        }
    }

    __syncthreads();
    if (t < 64) {
        float inv = 1.f / rowsum[t];
        rowsum[t] = inv;
        g_inv[((size_t)(b * HEADS + h) * NTOK) + row0 + t] = inv;
    }

    // reduce k-halves: wh=0 -> sc, wh=1 -> qs (Q dead; qs used with stride 68)
    {
        float* dstbuf = wh ? qs : sc;
#pragma unroll
        for (int i2 = 0; i2 < 2; i2++)
#pragma unroll
            for (int dt = 0; dt < 4; dt++)
                wmma::store_matrix_sync(&dstbuf[(wr * 32 + i2 * 16) * 68 + dt * 16],
                                        av[i2][dt], 68, wmma::mem_row_major);
    }
    __syncthreads();
    {
        // 64 rows x 16 f4 = 1024 f4, 8 per thread
#pragma unroll
        for (int i = 0; i < 8; i++) {
            int fi = t + (i << 7);
            int r = fi >> 4;
            int d4 = (fi & 15) << 2;
            float inv = rowsum[r];
            float4 a = *(const float4*)&sc[r * 68 + d4];
            float4 c = *(const float4*)&qs[r * 68 + d4];
            float4 o;
            o.x = (a.x + c.x) * inv;
            o.y = (a.y + c.y) * inv;
            o.z = (a.z + c.z) * inv;
            o.w = (a.w + c.w) * inv;
            float* dst = att_out + ((size_t)b * NTOK + row0 + r) * CHID + h * DIM + d4;
            *(float4*)dst = o;
        }
    }
}

// ---------------- normalize weights (roofline-bound) ----------------
__global__ __launch_bounds__(256) void normalize_w(float* __restrict__ w_out) {
    size_t nf4 = (size_t)BATCH * HEADS * NTOK * NTOK / 4;
    size_t stride = (size_t)gridDim.x * blockDim.x;
    for (size_t i = (size_t)blockIdx.x * blockDim.x + threadIdx.x; i < nf4; i += stride) {
        size_t fidx = i << 2;
        float inv = __ldg(&g_inv[fidx >> 11]);
        float4 v = *(float4*)(w_out + fidx);
        v.x *= inv; v.y *= inv; v.z *= inv; v.w *= inv;
        *(float4*)(w_out + fidx) = v;
    }
}

#define GEMM_SMEM (2 * (256 + 128) * SLD * 4)
#define ATT_SMEM ((64 * KLD + 2 * 128 * KLD + 64 * 68 + 64 + 2048) * 4 + 64)

extern "C" void kernel_launch(void* const* d_in, const int* in_sizes, int n_in,
                              void* d_out, int out_size) {
    (void)in_sizes; (void)n_in; (void)out_size;
    const float* X = (const float*)d_in[0];
    const float* W = (const float*)d_in[1];
    const void* mask = d_in[2];
    float* att = (float*)d_out;
    float* wts = (float*)d_out + (size_t)BATCH * NTOK * CHID;

    cudaFuncSetAttribute(qkv_gemm, cudaFuncAttributeMaxDynamicSharedMemorySize, GEMM_SMEM);
    cudaFuncSetAttribute(attn_fused, cudaFuncAttributeMaxDynamicSharedMemorySize, ATT_SMEM);

    qkv_gemm<<<dim3(24, 16), 256, GEMM_SMEM>>>(X, W);
    attn_fused<<<dim3(32, HEADS, BATCH), 128, ATT_SMEM>>>(mask, att, wts);
    normalize_w<<<4096, 256>>>(wts);
}